// round 11
// baseline (speedup 1.0000x reference)
#include <cuda_runtime.h>
#include <cuda_bf16.h>

// MoE noisy top-1 gating, N=262144, D=256, E=3.
//   logits = x@wg + noise * (softplus(x@wn) + 0.2);  out[t] = argmax (as float)
//
// R9 (resubmit after infra failure): R8 + per-token interleaved prefetch.
//  xa[q]/xb[q] are dead right after token q's FMA block, so the NEXT
//  iteration's loads for token q issue immediately there (in-place refill).
//  First prefetch launches ~1/4 into the iteration -> loads in flight for
//  ~85-90% of the loop instead of ~50%. Zero extra registers.

#define GATE_N 262144
#define GATE_D 256
#define GATE_E 3
#define NOISE_EPS 0.2f

__device__ __forceinline__ unsigned long long pk2(float lo, float hi) {
    unsigned long long r;
    asm("mov.b64 %0, {%1, %2};" : "=l"(r) : "f"(lo), "f"(hi));
    return r;
}
__device__ __forceinline__ void fma2(unsigned long long& acc,
                                     unsigned long long a,
                                     unsigned long long b) {
    asm("fma.rn.f32x2 %0, %1, %2, %0;" : "+l"(acc) : "l"(a), "l"(b));
}
__device__ __forceinline__ float unpk_sum(unsigned long long v) {
    float lo, hi;
    asm("mov.b64 {%0, %1}, %2;" : "=f"(lo), "=f"(hi) : "l"(v));
    return lo + hi;
}

__global__ __launch_bounds__(256, 2)
void moe_gate_kernel(const float* __restrict__ x,
                     const float* __restrict__ wg,
                     const float* __restrict__ wn,
                     const float* __restrict__ noise,
                     float* __restrict__ out)
{
    const int lane   = threadIdx.x & 31;
    const int gwarp  = (blockIdx.x * blockDim.x + threadIdx.x) >> 5;
    const int nwarps = (gridDim.x * blockDim.x) >> 5;
    const int stride = 4 * nwarps;

    // Lane owns dims {4l..4l+3} and {128+4l..128+4l+3} -> 4 f32x2 dim-pairs.
    unsigned long long wgp[4][3], wnp[4][3];
#pragma unroll
    for (int p = 0; p < 4; ++p) {
        const int d = (p < 2) ? (4 * lane + 2 * p) : (128 + 4 * lane + 2 * (p - 2));
#pragma unroll
        for (int e = 0; e < 3; ++e) {
            wgp[p][e] = pk2(__ldg(wg + d * 3 + e), __ldg(wg + (d + 1) * 3 + e));
            wnp[p][e] = pk2(__ldg(wn + d * 3 + e), __ldg(wn + (d + 1) * 3 + e));
        }
    }

    // Row = 256 floats = 64 ulonglong2. Lane reads idx lane and 32+lane.
    const ulonglong2* __restrict__ x2 = reinterpret_cast<const ulonglong2*>(x);

    const int quad  = lane >> 3;   // token this lane finalizes
    const int j     = lane & 7;    // role in quadrant (j<3 -> expert j)
    const int qbase = lane & 24;   // first lane of my quadrant

    int t0 = 4 * gwarp;
    if (t0 >= GATE_N) return;

    // ---- prologue loads ----
    ulonglong2 xa[4], xb[4];
#pragma unroll
    for (int q = 0; q < 4; ++q) {
        xa[q] = x2[(size_t)(t0 + q) * 64 + lane];
        xb[q] = x2[(size_t)(t0 + q) * 64 + 32 + lane];
    }
    float nsraw = (lane < 12) ? __ldg(noise + (size_t)t0 * 3 + lane) : 0.f;

    while (t0 < GATE_N) {
        const int tn = t0 + stride;
        const bool more = (tn < GATE_N);

        // ---- FMA phase with interleaved in-place prefetch ----
        float P[4][6];
#pragma unroll
        for (int q = 0; q < 4; ++q) {
            unsigned long long a0 = 0, a1 = 0, a2 = 0, a3 = 0, a4 = 0, a5 = 0;
            const unsigned long long xp[4] = {xa[q].x, xa[q].y, xb[q].x, xb[q].y};
#pragma unroll
            for (int p = 0; p < 4; ++p) {
                fma2(a0, xp[p], wgp[p][0]);
                fma2(a1, xp[p], wgp[p][1]);
                fma2(a2, xp[p], wgp[p][2]);
                fma2(a3, xp[p], wnp[p][0]);
                fma2(a4, xp[p], wnp[p][1]);
                fma2(a5, xp[p], wnp[p][2]);
            }
            // xa[q]/xb[q] are dead now -> refill for next iteration immediately.
            if (more) {
                xa[q] = x2[(size_t)(tn + q) * 64 + lane];
                xb[q] = x2[(size_t)(tn + q) * 64 + 32 + lane];
            }
            P[q][0] = unpk_sum(a0); P[q][1] = unpk_sum(a1); P[q][2] = unpk_sum(a2);
            P[q][3] = unpk_sum(a3); P[q][4] = unpk_sum(a4); P[q][5] = unpk_sum(a5);
        }

        // ---- noise prefetch for next iteration ----
        float nsn = 0.f;
        if (more && lane < 12) nsn = __ldg(noise + (size_t)tn * 3 + lane);

        // ---- fold round 1 (xor 16): T0<->T2, T1<->T3 ----
        const bool lo16 = (lane < 16);
        float U[6], W[6];
#pragma unroll
        for (int e = 0; e < 6; ++e) {
            const float u  = lo16 ? P[0][e] : P[2][e];
            const float uv = lo16 ? P[2][e] : P[0][e];
            U[e] = u + __shfl_xor_sync(0xFFFFFFFFu, uv, 16);
            const float w  = lo16 ? P[1][e] : P[3][e];
            const float wv = lo16 ? P[3][e] : P[1][e];
            W[e] = w + __shfl_xor_sync(0xFFFFFFFFu, wv, 16);
        }

        // ---- fold round 2 (xor 8): quadrant q holds token q ----
        const bool lo8 = ((lane & 8) == 0);
        float R[6];
#pragma unroll
        for (int e = 0; e < 6; ++e) {
            const float r  = lo8 ? U[e] : W[e];
            const float rv = lo8 ? W[e] : U[e];
            R[e] = r + __shfl_xor_sync(0xFFFFFFFFu, rv, 8);
        }

        // ---- butterfly within 8-lane quadrants ----
#pragma unroll
        for (int off = 4; off > 0; off >>= 1) {
#pragma unroll
            for (int e = 0; e < 6; ++e)
                R[e] += __shfl_xor_sync(0xFFFFFFFFu, R[e], off);
        }

        // ---- tail: lane 8q+j (j<3) owns expert j of token q ----
        const float nv = __shfl_sync(0xFFFFFFFFu, nsraw, 3 * quad + j);
        const float cg = (j == 1) ? R[1] : ((j == 2) ? R[2] : R[0]);
        const float cn = (j == 1) ? R[4] : ((j == 2) ? R[5] : R[3]);
        const float sp = fmaxf(cn, 0.f) + log1pf(expf(-fabsf(cn)));
        const float logit = fmaf(nv, sp + NOISE_EPS, cg);

        const float l1 = __shfl_sync(0xFFFFFFFFu, logit, qbase + 1);
        const float l2 = __shfl_sync(0xFFFFFFFFu, logit, qbase + 2);

        if (j == 0) {
            int   idx  = 0;
            float best = logit;          // expert 0
            if (l1 > best) { best = l1; idx = 1; }
            if (l2 > best) {            idx = 2; }
            out[t0 + quad] = (float)idx; // 4 lanes, 16B coalesced
        }

        // ---- rotate pipeline ----
        nsraw = nsn;
        t0 = tn;
    }
}

extern "C" void kernel_launch(void* const* d_in, const int* in_sizes, int n_in,
                              void* d_out, int out_size)
{
    // Resolve inputs BY SIZE (robust to metadata ordering).
    //   N*D -> input, N*E -> noise, D*E -> w_gate (first), w_noise (second)
    const float* x   = nullptr;
    const float* wg  = nullptr;
    const float* wn  = nullptr;
    const float* nse = nullptr;

    for (int i = 0; i < n_in; ++i) {
        const long long sz = in_sizes[i];
        if (sz == (long long)GATE_N * GATE_D) {
            x = (const float*)d_in[i];
        } else if (sz == (long long)GATE_N * GATE_E) {
            nse = (const float*)d_in[i];
        } else if (sz == (long long)GATE_D * GATE_E) {
            if (!wg) wg = (const float*)d_in[i];
            else     wn = (const float*)d_in[i];
        }
    }

    float* out = (float*)d_out;
    (void)out_size;

    moe_gate_kernel<<<592, 256>>>(x, wg, wn, nse, out);
}